// round 1
// baseline (speedup 1.0000x reference)
#include <cuda_runtime.h>
#include <math.h>

#define B_ 4
#define N_ 1024
#define C_ 768
#define H_ 12
#define DH 64
#define QT 16          // query rows per attention block
#define KT 128         // key rows per smem tile
#define TOPK 128

#define OUT0 (B_*N_*C_)   // offset of score_delta in d_out

// ---------------- scratch (device globals; no allocation allowed) ----------
__device__ float g_q[B_*H_*N_*DH];
__device__ float g_k[B_*H_*N_*DH];
__device__ float g_v[B_*H_*N_*DH];
__device__ float g_ctx[B_*H_*N_*DH];

// ---------------- helpers ----------------
__device__ __forceinline__ unsigned fkey(float f) {
    unsigned u = __float_as_uint(f);
    return (u & 0x80000000u) ? ~u : (u | 0x80000000u); // order-preserving float->uint
}
__device__ __forceinline__ float wredsum(float v) {
    #pragma unroll
    for (int o = 16; o; o >>= 1) v += __shfl_xor_sync(0xffffffffu, v, o);
    return v;
}
__device__ __forceinline__ float wredmax(float v) {
    #pragma unroll
    for (int o = 16; o; o >>= 1) v = fmaxf(v, __shfl_xor_sync(0xffffffffu, v, o));
    return v;
}

// ---------------- QKV GEMM:  y[m,o] = sum_k x[m,k] * W[o,k] ----------------
// 64x64 block tile, 16 k-tile, 256 threads, 4x4 microtile.
// Output scattered into g_q/g_k/g_v with layout [B,H,N,Dh].
__global__ __launch_bounds__(256) void qkv_gemm(const float* __restrict__ X,
                                                const float* __restrict__ W)
{
    __shared__ float As[16][68];   // [k][m]
    __shared__ float Bs[16][68];   // [k][o]
    const int m0 = blockIdx.y * 64;
    const int o0 = blockIdx.x * 64;
    const int tid  = threadIdx.x;
    const int lrow = tid >> 2;            // 0..63
    const int lc4  = (tid & 3) << 2;      // 0,4,8,12
    const int tm = tid >> 4;              // 0..15
    const int to = tid & 15;              // 0..15

    float acc[4][4];
    #pragma unroll
    for (int i = 0; i < 4; i++)
        #pragma unroll
        for (int j = 0; j < 4; j++) acc[i][j] = 0.f;

    for (int k0 = 0; k0 < C_; k0 += 16) {
        float4 av = *(const float4*)&X[(m0 + lrow) * C_ + k0 + lc4];
        float4 bv = *(const float4*)&W[(o0 + lrow) * C_ + k0 + lc4];
        __syncthreads();
        As[lc4+0][lrow] = av.x; As[lc4+1][lrow] = av.y;
        As[lc4+2][lrow] = av.z; As[lc4+3][lrow] = av.w;
        Bs[lc4+0][lrow] = bv.x; Bs[lc4+1][lrow] = bv.y;
        Bs[lc4+2][lrow] = bv.z; Bs[lc4+3][lrow] = bv.w;
        __syncthreads();
        #pragma unroll
        for (int kk = 0; kk < 16; kk++) {
            float4 a = *(const float4*)&As[kk][tm * 4];
            float4 b = *(const float4*)&Bs[kk][to * 4];
            float aa[4] = {a.x, a.y, a.z, a.w};
            float bb[4] = {b.x, b.y, b.z, b.w};
            #pragma unroll
            for (int i = 0; i < 4; i++)
                #pragma unroll
                for (int j = 0; j < 4; j++) acc[i][j] += aa[i] * bb[j];
        }
    }
    // epilogue: o-block of 64 lies within one (part, head)
    const int part = o0 / C_;
    const int h    = (o0 % C_) / DH;
    const int b    = m0 / N_;
    const int n0   = m0 % N_;
    float* dst = (part == 0) ? g_q : (part == 1) ? g_k : g_v;
    #pragma unroll
    for (int i = 0; i < 4; i++) {
        int n = n0 + tm * 4 + i;
        float4 v = make_float4(acc[i][0], acc[i][1], acc[i][2], acc[i][3]);
        *(float4*)&dst[(((b * H_ + h) * N_) + n) * DH + to * 4] = v;
    }
}

// ---------------- Proj GEMM: out[m,o] = sum_k ctx_perm[m,k]*W[o,k] + b[o] ---
__global__ __launch_bounds__(256) void proj_gemm(const float* __restrict__ W,
                                                 const float* __restrict__ bias,
                                                 float* __restrict__ out)
{
    __shared__ float As[16][68];
    __shared__ float Bs[16][68];
    const int m0 = blockIdx.y * 64;
    const int o0 = blockIdx.x * 64;
    const int tid  = threadIdx.x;
    const int lrow = tid >> 2;
    const int lc4  = (tid & 3) << 2;
    const int tm = tid >> 4;
    const int to = tid & 15;

    const int m = m0 + lrow;
    const int bb_ = m >> 10;          // batch
    const int n   = m & 1023;

    float acc[4][4];
    #pragma unroll
    for (int i = 0; i < 4; i++)
        #pragma unroll
        for (int j = 0; j < 4; j++) acc[i][j] = 0.f;

    for (int k0 = 0; k0 < C_; k0 += 16) {
        const int k = k0 + lc4;
        const int h = k >> 6;
        const int d = k & 63;
        float4 av = *(const float4*)&g_ctx[(((bb_ * H_ + h) * N_) + n) * DH + d];
        float4 bv = *(const float4*)&W[(o0 + lrow) * C_ + k0 + lc4];
        __syncthreads();
        As[lc4+0][lrow] = av.x; As[lc4+1][lrow] = av.y;
        As[lc4+2][lrow] = av.z; As[lc4+3][lrow] = av.w;
        Bs[lc4+0][lrow] = bv.x; Bs[lc4+1][lrow] = bv.y;
        Bs[lc4+2][lrow] = bv.z; Bs[lc4+3][lrow] = bv.w;
        __syncthreads();
        #pragma unroll
        for (int kk = 0; kk < 16; kk++) {
            float4 a = *(const float4*)&As[kk][tm * 4];
            float4 b = *(const float4*)&Bs[kk][to * 4];
            float aa[4] = {a.x, a.y, a.z, a.w};
            float bvv[4] = {b.x, b.y, b.z, b.w};
            #pragma unroll
            for (int i = 0; i < 4; i++)
                #pragma unroll
                for (int j = 0; j < 4; j++) acc[i][j] += aa[i] * bvv[j];
        }
    }
    float4 bsv = *(const float4*)&bias[o0 + to * 4];
    float bb4[4] = {bsv.x, bsv.y, bsv.z, bsv.w};
    #pragma unroll
    for (int i = 0; i < 4; i++) {
        int mo = m0 + tm * 4 + i;
        float4 v = make_float4(acc[i][0] + bb4[0], acc[i][1] + bb4[1],
                               acc[i][2] + bb4[2], acc[i][3] + bb4[3]);
        *(float4*)&out[mo * C_ + o0 + to * 4] = v;
    }
}

// ---------------- Attention core ------------------------------------------
// One block per (h, 16-query tile). Handles all 4 batches:
//   scores (regs, per-warp 2 rows) -> softmax stats -> exact radix top-128
//   -> sparse renormalized context -> score_delta (mask count over b).
#define SMEM_ATTN (16384 + 65536 + 34816 + 8192 + 4096 + 16384 + 8192 + 64)

__global__ __launch_bounds__(256, 1) void attn_kernel(const float* __restrict__ cnt,
                                                      const int* __restrict__ counter_p,
                                                      float* __restrict__ sd)
{
    extern __shared__ char smem[];
    float*          sQ    = (float*)smem;                         // [4][16][64]   16KB
    float*          sExpl = sQ + B_*QT*DH;                        // [16][1024]    64KB
    float*          sK    = sExpl + QT*N_;                        // [128][68]     34KB
    float*          wlist = sK + KT*68;                           // [16][128]      8KB
    unsigned short* idxl  = (unsigned short*)(wlist + QT*TOPK);   // [16][128]      4KB
    unsigned char*  mcnt  = (unsigned char*)(idxl + QT*TOPK);     // [16][1024]    16KB
    int*            hist  = (int*)(mcnt + QT*N_);                 // [8][256]       8KB
    int*            rowCnt= hist + 8*256;                         // [16]

    const int h    = blockIdx.y;
    const int q0   = blockIdx.x * QT;
    const int tid  = threadIdx.x;
    const int lane = tid & 31;
    const int w    = tid >> 5;
    const float logc = logf((float)(*counter_p) + 1.0f);

    // zero mask counts
    for (int i = tid; i < QT*N_/4; i += 256) ((unsigned int*)mcnt)[i] = 0u;

    // load Q (pre-scaled by Dh^-0.5 = 0.125)
    for (int i = tid; i < B_*QT*DH/4; i += 256) {
        int b  = i >> 8;
        int r  = (i >> 4) & 15;
        int d4 = (i & 15) << 2;
        float4 v = *(const float4*)&g_q[(((b*H_ + h)*N_) + q0 + r)*DH + d4];
        float4 sv = make_float4(v.x*0.125f, v.y*0.125f, v.z*0.125f, v.w*0.125f);
        *(float4*)&sQ[(b*QT + r)*DH + d4] = sv;
    }
    // exploration bonus (batch-independent): sqrt(log(counter+1)/(count+1e-6))
    for (int i = tid; i < QT*N_/4; i += 256) {
        int r  = i >> 8;
        int j4 = (i & 255) << 2;
        float4 c = *(const float4*)&cnt[(h*N_ + q0 + r)*N_ + j4];
        float4 e;
        e.x = sqrtf(logc / (c.x + 1e-6f));
        e.y = sqrtf(logc / (c.y + 1e-6f));
        e.z = sqrtf(logc / (c.z + 1e-6f));
        e.w = sqrtf(logc / (c.w + 1e-6f));
        *(float4*)&sExpl[r*N_ + j4] = e;
    }
    __syncthreads();

    float sreg[2][8][4];  // warp w owns rows 2w, 2w+1; lane covers j = t*128+u*32+lane

    for (int b = 0; b < B_; b++) {
        const float* Kb = &g_k[((b*H_ + h)*N_)*DH];
        const float* Vb = &g_v[((b*H_ + h)*N_)*DH];

        // ---- scores: S[16][1024] into registers, 8 K-tiles of 128 rows ----
        #pragma unroll
        for (int tile = 0; tile < 8; tile++) {
            __syncthreads();
            for (int i = tid; i < KT*16; i += 256) {
                int row = i >> 4;
                int c4  = (i & 15) << 2;
                float4 v = *(const float4*)&Kb[(tile*KT + row)*DH + c4];
                *(float4*)&sK[row*68 + c4] = v;
            }
            __syncthreads();
            float a0[4] = {0.f,0.f,0.f,0.f};
            float a1[4] = {0.f,0.f,0.f,0.f};
            #pragma unroll
            for (int kk4 = 0; kk4 < 16; kk4++) {
                float4 qa = *(const float4*)&sQ[(b*QT + 2*w    )*DH + kk4*4];
                float4 qb = *(const float4*)&sQ[(b*QT + 2*w + 1)*DH + kk4*4];
                #pragma unroll
                for (int u = 0; u < 4; u++) {
                    float4 kv = *(const float4*)&sK[(u*32 + lane)*68 + kk4*4];
                    a0[u] += qa.x*kv.x + qa.y*kv.y + qa.z*kv.z + qa.w*kv.w;
                    a1[u] += qb.x*kv.x + qb.y*kv.y + qb.z*kv.z + qb.w*kv.w;
                }
            }
            #pragma unroll
            for (int u = 0; u < 4; u++) { sreg[0][tile][u] = a0[u]; sreg[1][tile][u] = a1[u]; }
        }

        // ---- per-row: softmax stats, radix top-k, selection ----
        #pragma unroll
        for (int qp = 0; qp < 2; qp++) {
            const int r = 2*w + qp;
            // row max and full softmax denominator Z
            float m = -1e30f;
            #pragma unroll
            for (int t = 0; t < 8; t++)
                #pragma unroll
                for (int u = 0; u < 4; u++) m = fmaxf(m, sreg[qp][t][u]);
            m = wredmax(m);
            float z = 0.f;
            #pragma unroll
            for (int t = 0; t < 8; t++)
                #pragma unroll
                for (int u = 0; u < 4; u++) z += __expf(sreg[qp][t][u] - m);
            z = wredsum(z);

            // exact 128th-largest of key(s + expl) via 4x8-bit radix select
            int* hw = hist + w*256;
            unsigned prefix = 0; int want = TOPK;
            #pragma unroll
            for (int shift = 24; shift >= 0; shift -= 8) {
                for (int i = lane; i < 256; i += 32) hw[i] = 0;
                __syncwarp();
                unsigned mhi = (shift == 24) ? 0u : (0xffffffffu << (shift + 8));
                #pragma unroll
                for (int t = 0; t < 8; t++)
                    #pragma unroll
                    for (int u = 0; u < 4; u++) {
                        int j = t*128 + u*32 + lane;
                        unsigned key = fkey(sreg[qp][t][u] + sExpl[r*N_ + j]);
                        if ((key & mhi) == prefix) atomicAdd(&hw[(key >> shift) & 255], 1);
                    }
                __syncwarp();
                int s8 = 0;
                #pragma unroll
                for (int i = 0; i < 8; i++) s8 += hw[lane*8 + i];
                int suf = s8;   // inclusive suffix sum over lanes (lane..31)
                #pragma unroll
                for (int off = 1; off < 32; off <<= 1) {
                    int v = __shfl_down_sync(0xffffffffu, suf, off);
                    if (lane + off < 32) suf += v;
                }
                unsigned bal = __ballot_sync(0xffffffffu, (suf >= want) && (suf - s8 < want));
                int lsel = __ffs(bal) - 1;
                int above = __shfl_sync(0xffffffffu, suf - s8, lsel);
                int digit = 0, nwant = 0;
                if (lane == lsel) {
                    int c = above;
                    for (int d2 = lane*8 + 7; d2 >= lane*8; d2--) {
                        int hc = hw[d2];
                        if (c + hc >= want) { digit = d2; nwant = want - c; break; }
                        c += hc;
                    }
                }
                digit = __shfl_sync(0xffffffffu, digit, lsel);
                want  = __shfl_sync(0xffffffffu, nwant, lsel);
                prefix |= ((unsigned)(digit & 255)) << shift;
            }
            const unsigned T = prefix;

            if (lane == 0) rowCnt[r] = 0;
            __syncwarp();
            float esum = 0.f;
            #pragma unroll
            for (int t = 0; t < 8; t++)
                #pragma unroll
                for (int u = 0; u < 4; u++) {
                    int j = t*128 + u*32 + lane;
                    float s = sreg[qp][t][u];
                    unsigned key = fkey(s + sExpl[r*N_ + j]);
                    if (key >= T) {
                        float e = __expf(s - m);
                        esum += e;
                        int pos = atomicAdd(&rowCnt[r], 1);
                        if (pos < TOPK) {
                            idxl[r*TOPK + pos]  = (unsigned short)j;
                            wlist[r*TOPK + pos] = e;
                        }
                        mcnt[r*N_ + j] = (unsigned char)(mcnt[r*N_ + j] + 1);
                    }
                }
            float smask = wredsum(esum);
            float inv = 1.f / (smask + 1e-8f * z);
            __syncwarp();
            for (int i = lane; i < TOPK; i += 32) wlist[r*TOPK + i] *= inv;
            __syncwarp();
        }
        __syncthreads();

        // ---- sparse context: ctx[b,h,r,:] = sum over 128 selected j ----
        {
            const int r  = tid >> 4;
            const int d4 = (tid & 15) << 2;
            float4 a = make_float4(0.f, 0.f, 0.f, 0.f);
            #pragma unroll 4
            for (int i = 0; i < TOPK; i++) {
                int   j  = idxl[r*TOPK + i];
                float ww = wlist[r*TOPK + i];
                float4 vv = *(const float4*)&Vb[j*DH + d4];
                a.x += ww*vv.x; a.y += ww*vv.y; a.z += ww*vv.z; a.w += ww*vv.w;
            }
            *(float4*)&g_ctx[(((b*H_ + h)*N_) + q0 + r)*DH + d4] = a;
        }
    }
    __syncthreads();

    // ---- score_delta = sum over batch of mask, dense write ----
    for (int i = tid; i < QT*N_/4; i += 256) {
        int r  = i >> 8;
        int j4 = i & 255;
        unsigned mv = ((unsigned*)mcnt)[r*256 + j4];
        float4 o;
        o.x = (float)( mv        & 255u);
        o.y = (float)((mv >>  8) & 255u);
        o.z = (float)((mv >> 16) & 255u);
        o.w = (float)((mv >> 24) & 255u);
        *(float4*)&sd[(h*N_ + q0 + r)*N_ + (j4 << 2)] = o;
    }
}

// ---------------- launch ---------------------------------------------------
extern "C" void kernel_launch(void* const* d_in, const int* in_sizes, int n_in,
                              void* d_out, int out_size)
{
    const float* x     = (const float*)d_in[0];
    const float* qkvw  = (const float*)d_in[1];
    const float* projw = (const float*)d_in[2];
    const float* projb = (const float*)d_in[3];
    const float* ucb   = (const float*)d_in[4];
    const int*   ctr   = (const int*)d_in[5];
    float* out = (float*)d_out;
    float* sd  = out + OUT0;

    cudaFuncSetAttribute(attn_kernel, cudaFuncAttributeMaxDynamicSharedMemorySize, SMEM_ATTN);

    qkv_gemm<<<dim3(36, 64), 256>>>(x, qkvw);
    attn_kernel<<<dim3(64, 12), 256, SMEM_ATTN>>>(ucb, ctr, sd);
    proj_gemm<<<dim3(12, 64), 256>>>(projw, projb, out);
}

// round 2
// speedup vs baseline: 1.0097x; 1.0097x over previous
#include <cuda_runtime.h>
#include <math.h>

#define B_ 4
#define N_ 1024
#define C_ 768
#define H_ 12
#define DH 64
#define QT 16          // query rows per attention block
#define KT 128         // key rows per smem tile
#define TOPK 128

#define OUT0 (B_*N_*C_)   // offset of score_delta in d_out

// ---------------- scratch (device globals; no allocation allowed) ----------
__device__ float g_q[B_*H_*N_*DH];
__device__ float g_k[B_*H_*N_*DH];
__device__ float g_v[B_*H_*N_*DH];
__device__ float g_ctx[B_*H_*N_*DH];

// ---------------- helpers ----------------
__device__ __forceinline__ unsigned fkey(float f) {
    unsigned u = __float_as_uint(f);
    return (u & 0x80000000u) ? ~u : (u | 0x80000000u); // order-preserving float->uint
}
__device__ __forceinline__ float wredsum(float v) {
    #pragma unroll
    for (int o = 16; o; o >>= 1) v += __shfl_xor_sync(0xffffffffu, v, o);
    return v;
}
__device__ __forceinline__ float wredmax(float v) {
    #pragma unroll
    for (int o = 16; o; o >>= 1) v = fmaxf(v, __shfl_xor_sync(0xffffffffu, v, o));
    return v;
}

// ---------------- QKV GEMM:  y[m,o] = sum_k x[m,k] * W[o,k] ----------------
// 64x64 block tile, 16 k-tile, 256 threads, 4x4 microtile.
// Output scattered into g_q/g_k/g_v with layout [B,H,N,Dh].
__global__ __launch_bounds__(256) void qkv_gemm(const float* __restrict__ X,
                                                const float* __restrict__ W)
{
    __shared__ float As[16][68];   // [k][m]
    __shared__ float Bs[16][68];   // [k][o]
    const int m0 = blockIdx.y * 64;
    const int o0 = blockIdx.x * 64;
    const int tid  = threadIdx.x;
    const int lrow = tid >> 2;            // 0..63
    const int lc4  = (tid & 3) << 2;      // 0,4,8,12
    const int tm = tid >> 4;              // 0..15
    const int to = tid & 15;              // 0..15

    float acc[4][4];
    #pragma unroll
    for (int i = 0; i < 4; i++)
        #pragma unroll
        for (int j = 0; j < 4; j++) acc[i][j] = 0.f;

    for (int k0 = 0; k0 < C_; k0 += 16) {
        float4 av = *(const float4*)&X[(m0 + lrow) * C_ + k0 + lc4];
        float4 bv = *(const float4*)&W[(o0 + lrow) * C_ + k0 + lc4];
        __syncthreads();
        As[lc4+0][lrow] = av.x; As[lc4+1][lrow] = av.y;
        As[lc4+2][lrow] = av.z; As[lc4+3][lrow] = av.w;
        Bs[lc4+0][lrow] = bv.x; Bs[lc4+1][lrow] = bv.y;
        Bs[lc4+2][lrow] = bv.z; Bs[lc4+3][lrow] = bv.w;
        __syncthreads();
        #pragma unroll
        for (int kk = 0; kk < 16; kk++) {
            float4 a = *(const float4*)&As[kk][tm * 4];
            float4 b = *(const float4*)&Bs[kk][to * 4];
            float aa[4] = {a.x, a.y, a.z, a.w};
            float bb[4] = {b.x, b.y, b.z, b.w};
            #pragma unroll
            for (int i = 0; i < 4; i++)
                #pragma unroll
                for (int j = 0; j < 4; j++) acc[i][j] += aa[i] * bb[j];
        }
    }
    // epilogue: o-block of 64 lies within one (part, head)
    const int part = o0 / C_;
    const int h    = (o0 % C_) / DH;
    const int b    = m0 / N_;
    const int n0   = m0 % N_;
    float* dst = (part == 0) ? g_q : (part == 1) ? g_k : g_v;
    #pragma unroll
    for (int i = 0; i < 4; i++) {
        int n = n0 + tm * 4 + i;
        float4 v = make_float4(acc[i][0], acc[i][1], acc[i][2], acc[i][3]);
        *(float4*)&dst[(((b * H_ + h) * N_) + n) * DH + to * 4] = v;
    }
}

// ---------------- Proj GEMM: out[m,o] = sum_k ctx_perm[m,k]*W[o,k] + b[o] ---
__global__ __launch_bounds__(256) void proj_gemm(const float* __restrict__ W,
                                                 const float* __restrict__ bias,
                                                 float* __restrict__ out)
{
    __shared__ float As[16][68];
    __shared__ float Bs[16][68];
    const int m0 = blockIdx.y * 64;
    const int o0 = blockIdx.x * 64;
    const int tid  = threadIdx.x;
    const int lrow = tid >> 2;
    const int lc4  = (tid & 3) << 2;
    const int tm = tid >> 4;
    const int to = tid & 15;

    const int m = m0 + lrow;
    const int bb_ = m >> 10;          // batch
    const int n   = m & 1023;

    float acc[4][4];
    #pragma unroll
    for (int i = 0; i < 4; i++)
        #pragma unroll
        for (int j = 0; j < 4; j++) acc[i][j] = 0.f;

    for (int k0 = 0; k0 < C_; k0 += 16) {
        const int k = k0 + lc4;
        const int h = k >> 6;
        const int d = k & 63;
        float4 av = *(const float4*)&g_ctx[(((bb_ * H_ + h) * N_) + n) * DH + d];
        float4 bv = *(const float4*)&W[(o0 + lrow) * C_ + k0 + lc4];
        __syncthreads();
        As[lc4+0][lrow] = av.x; As[lc4+1][lrow] = av.y;
        As[lc4+2][lrow] = av.z; As[lc4+3][lrow] = av.w;
        Bs[lc4+0][lrow] = bv.x; Bs[lc4+1][lrow] = bv.y;
        Bs[lc4+2][lrow] = bv.z; Bs[lc4+3][lrow] = bv.w;
        __syncthreads();
        #pragma unroll
        for (int kk = 0; kk < 16; kk++) {
            float4 a = *(const float4*)&As[kk][tm * 4];
            float4 b = *(const float4*)&Bs[kk][to * 4];
            float aa[4] = {a.x, a.y, a.z, a.w};
            float bvv[4] = {b.x, b.y, b.z, b.w};
            #pragma unroll
            for (int i = 0; i < 4; i++)
                #pragma unroll
                for (int j = 0; j < 4; j++) acc[i][j] += aa[i] * bvv[j];
        }
    }
    float4 bsv = *(const float4*)&bias[o0 + to * 4];
    float bb4[4] = {bsv.x, bsv.y, bsv.z, bsv.w};
    #pragma unroll
    for (int i = 0; i < 4; i++) {
        int mo = m0 + tm * 4 + i;
        float4 v = make_float4(acc[i][0] + bb4[0], acc[i][1] + bb4[1],
                               acc[i][2] + bb4[2], acc[i][3] + bb4[3]);
        *(float4*)&out[mo * C_ + o0 + to * 4] = v;
    }
}

// ---------------- Attention core ------------------------------------------
// One block per (h, 16-query tile). Handles all 4 batches:
//   scores (regs, per-warp 2 rows) -> softmax stats -> exact radix top-128
//   -> sparse renormalized context -> score_delta (mask count over b).
#define SMEM_ATTN (16384 + 65536 + 34816 + 8192 + 4096 + 16384 + 8192 + 64)

__global__ __launch_bounds__(256, 1) void attn_kernel(const float* __restrict__ cnt,
                                                      const int* __restrict__ counter_p,
                                                      float* __restrict__ sd)
{
    extern __shared__ char smem[];
    float*          sQ    = (float*)smem;                         // [4][16][64]   16KB
    float*          sExpl = sQ + B_*QT*DH;                        // [16][1024]    64KB
    float*          sK    = sExpl + QT*N_;                        // [128][68]     34KB
    float*          wlist = sK + KT*68;                           // [16][128]      8KB
    unsigned short* idxl  = (unsigned short*)(wlist + QT*TOPK);   // [16][128]      4KB
    unsigned char*  mcnt  = (unsigned char*)(idxl + QT*TOPK);     // [16][1024]    16KB
    int*            hist  = (int*)(mcnt + QT*N_);                 // [8][256]       8KB
    int*            rowCnt= hist + 8*256;                         // [16]

    const int h    = blockIdx.y;
    const int q0   = blockIdx.x * QT;
    const int tid  = threadIdx.x;
    const int lane = tid & 31;
    const int w    = tid >> 5;
    const float logc = logf((float)(*counter_p) + 1.0f);

    // zero mask counts
    for (int i = tid; i < QT*N_/4; i += 256) ((unsigned int*)mcnt)[i] = 0u;

    // load Q (pre-scaled by Dh^-0.5 = 0.125)
    for (int i = tid; i < B_*QT*DH/4; i += 256) {
        int b  = i >> 8;
        int r  = (i >> 4) & 15;
        int d4 = (i & 15) << 2;
        float4 v = *(const float4*)&g_q[(((b*H_ + h)*N_) + q0 + r)*DH + d4];
        float4 sv = make_float4(v.x*0.125f, v.y*0.125f, v.z*0.125f, v.w*0.125f);
        *(float4*)&sQ[(b*QT + r)*DH + d4] = sv;
    }
    // exploration bonus (batch-independent): sqrt(log(counter+1)/(count+1e-6))
    for (int i = tid; i < QT*N_/4; i += 256) {
        int r  = i >> 8;
        int j4 = (i & 255) << 2;
        float4 c = *(const float4*)&cnt[(h*N_ + q0 + r)*N_ + j4];
        float4 e;
        e.x = sqrtf(logc / (c.x + 1e-6f));
        e.y = sqrtf(logc / (c.y + 1e-6f));
        e.z = sqrtf(logc / (c.z + 1e-6f));
        e.w = sqrtf(logc / (c.w + 1e-6f));
        *(float4*)&sExpl[r*N_ + j4] = e;
    }
    __syncthreads();

    float sreg[2][8][4];  // warp w owns rows 2w, 2w+1; lane covers j = t*128+u*32+lane

    for (int b = 0; b < B_; b++) {
        const float* Kb = &g_k[((b*H_ + h)*N_)*DH];
        const float* Vb = &g_v[((b*H_ + h)*N_)*DH];

        // ---- scores: S[16][1024] into registers, 8 K-tiles of 128 rows ----
        #pragma unroll
        for (int tile = 0; tile < 8; tile++) {
            __syncthreads();
            for (int i = tid; i < KT*16; i += 256) {
                int row = i >> 4;
                int c4  = (i & 15) << 2;
                float4 v = *(const float4*)&Kb[(tile*KT + row)*DH + c4];
                *(float4*)&sK[row*68 + c4] = v;
            }
            __syncthreads();
            float a0[4] = {0.f,0.f,0.f,0.f};
            float a1[4] = {0.f,0.f,0.f,0.f};
            #pragma unroll
            for (int kk4 = 0; kk4 < 16; kk4++) {
                float4 qa = *(const float4*)&sQ[(b*QT + 2*w    )*DH + kk4*4];
                float4 qb = *(const float4*)&sQ[(b*QT + 2*w + 1)*DH + kk4*4];
                #pragma unroll
                for (int u = 0; u < 4; u++) {
                    float4 kv = *(const float4*)&sK[(u*32 + lane)*68 + kk4*4];
                    a0[u] += qa.x*kv.x + qa.y*kv.y + qa.z*kv.z + qa.w*kv.w;
                    a1[u] += qb.x*kv.x + qb.y*kv.y + qb.z*kv.z + qb.w*kv.w;
                }
            }
            #pragma unroll
            for (int u = 0; u < 4; u++) { sreg[0][tile][u] = a0[u]; sreg[1][tile][u] = a1[u]; }
        }

        // ---- per-row: softmax stats, radix top-k, selection ----
        #pragma unroll
        for (int qp = 0; qp < 2; qp++) {
            const int r = 2*w + qp;
            // row max and full softmax denominator Z
            float m = -1e30f;
            #pragma unroll
            for (int t = 0; t < 8; t++)
                #pragma unroll
                for (int u = 0; u < 4; u++) m = fmaxf(m, sreg[qp][t][u]);
            m = wredmax(m);
            float z = 0.f;
            #pragma unroll
            for (int t = 0; t < 8; t++)
                #pragma unroll
                for (int u = 0; u < 4; u++) z += __expf(sreg[qp][t][u] - m);
            z = wredsum(z);

            // exact 128th-largest of key(s + expl) via 4x8-bit radix select
            int* hw = hist + w*256;
            unsigned prefix = 0; int want = TOPK;
            #pragma unroll
            for (int shift = 24; shift >= 0; shift -= 8) {
                for (int i = lane; i < 256; i += 32) hw[i] = 0;
                __syncwarp();
                unsigned mhi = (shift == 24) ? 0u : (0xffffffffu << (shift + 8));
                #pragma unroll
                for (int t = 0; t < 8; t++)
                    #pragma unroll
                    for (int u = 0; u < 4; u++) {
                        int j = t*128 + u*32 + lane;
                        unsigned key = fkey(sreg[qp][t][u] + sExpl[r*N_ + j]);
                        if ((key & mhi) == prefix) atomicAdd(&hw[(key >> shift) & 255], 1);
                    }
                __syncwarp();
                int s8 = 0;
                #pragma unroll
                for (int i = 0; i < 8; i++) s8 += hw[lane*8 + i];
                int suf = s8;   // inclusive suffix sum over lanes (lane..31)
                #pragma unroll
                for (int off = 1; off < 32; off <<= 1) {
                    int v = __shfl_down_sync(0xffffffffu, suf, off);
                    if (lane + off < 32) suf += v;
                }
                unsigned bal = __ballot_sync(0xffffffffu, (suf >= want) && (suf - s8 < want));
                int lsel = __ffs(bal) - 1;
                int above = __shfl_sync(0xffffffffu, suf - s8, lsel);
                int digit = 0, nwant = 0;
                if (lane == lsel) {
                    int c = above;
                    for (int d2 = lane*8 + 7; d2 >= lane*8; d2--) {
                        int hc = hw[d2];
                        if (c + hc >= want) { digit = d2; nwant = want - c; break; }
                        c += hc;
                    }
                }
                digit = __shfl_sync(0xffffffffu, digit, lsel);
                want  = __shfl_sync(0xffffffffu, nwant, lsel);
                prefix |= ((unsigned)(digit & 255)) << shift;
            }
            const unsigned T = prefix;

            if (lane == 0) rowCnt[r] = 0;
            __syncwarp();
            float esum = 0.f;
            #pragma unroll
            for (int t = 0; t < 8; t++)
                #pragma unroll
                for (int u = 0; u < 4; u++) {
                    int j = t*128 + u*32 + lane;
                    float s = sreg[qp][t][u];
                    unsigned key = fkey(s + sExpl[r*N_ + j]);
                    if (key >= T) {
                        float e = __expf(s - m);
                        esum += e;
                        int pos = atomicAdd(&rowCnt[r], 1);
                        if (pos < TOPK) {
                            idxl[r*TOPK + pos]  = (unsigned short)j;
                            wlist[r*TOPK + pos] = e;
                        }
                        mcnt[r*N_ + j] = (unsigned char)(mcnt[r*N_ + j] + 1);
                    }
                }
            float smask = wredsum(esum);
            float inv = 1.f / (smask + 1e-8f * z);
            __syncwarp();
            for (int i = lane; i < TOPK; i += 32) wlist[r*TOPK + i] *= inv;
            __syncwarp();
        }
        __syncthreads();

        // ---- sparse context: ctx[b,h,r,:] = sum over 128 selected j ----
        {
            const int r  = tid >> 4;
            const int d4 = (tid & 15) << 2;
            float4 a = make_float4(0.f, 0.f, 0.f, 0.f);
            #pragma unroll 4
            for (int i = 0; i < TOPK; i++) {
                int   j  = idxl[r*TOPK + i];
                float ww = wlist[r*TOPK + i];
                float4 vv = *(const float4*)&Vb[j*DH + d4];
                a.x += ww*vv.x; a.y += ww*vv.y; a.z += ww*vv.z; a.w += ww*vv.w;
            }
            *(float4*)&g_ctx[(((b*H_ + h)*N_) + q0 + r)*DH + d4] = a;
        }
    }
    __syncthreads();

    // ---- score_delta = sum over batch of mask, dense write ----
    for (int i = tid; i < QT*N_/4; i += 256) {
        int r  = i >> 8;
        int j4 = i & 255;
        unsigned mv = ((unsigned*)mcnt)[r*256 + j4];
        float4 o;
        o.x = (float)( mv        & 255u);
        o.y = (float)((mv >>  8) & 255u);
        o.z = (float)((mv >> 16) & 255u);
        o.w = (float)((mv >> 24) & 255u);
        *(float4*)&sd[(h*N_ + q0 + r)*N_ + (j4 << 2)] = o;
    }
}

// ---------------- launch ---------------------------------------------------
extern "C" void kernel_launch(void* const* d_in, const int* in_sizes, int n_in,
                              void* d_out, int out_size)
{
    const float* x     = (const float*)d_in[0];
    const float* qkvw  = (const float*)d_in[1];
    const float* projw = (const float*)d_in[2];
    const float* projb = (const float*)d_in[3];
    const float* ucb   = (const float*)d_in[4];
    const int*   ctr   = (const int*)d_in[5];
    float* out = (float*)d_out;
    float* sd  = out + OUT0;

    cudaFuncSetAttribute(attn_kernel, cudaFuncAttributeMaxDynamicSharedMemorySize, SMEM_ATTN);

    qkv_gemm<<<dim3(36, 64), 256>>>(x, qkvw);
    attn_kernel<<<dim3(64, 12), 256, SMEM_ATTN>>>(ucb, ctr, sd);
    proj_gemm<<<dim3(12, 64), 256>>>(projw, projb, out);
}

// round 4
// speedup vs baseline: 1.3948x; 1.3814x over previous
#include <cuda_runtime.h>
#include <math.h>

#define B_ 4
#define N_ 1024
#define C_ 768
#define H_ 12
#define DH 64
#define QT 16
#define TOPK 128

#define OUT0 (B_*N_*C_)

typedef unsigned long long ull;

// ---------------- scratch ----------------
__device__ float g_q[B_*H_*N_*DH];
__device__ float g_kT[B_*H_*DH*N_];   // transposed: [b][h][d][n]
__device__ float g_v[B_*H_*N_*DH];
__device__ float g_ctx[B_*H_*N_*DH];

// ---------------- helpers ----------------
__device__ __forceinline__ void ffma2(ull& d, ull a, ull b) {
    asm("fma.rn.f32x2 %0, %1, %2, %0;" : "+l"(d) : "l"(a), "l"(b));
}
__device__ __forceinline__ float2 u2f(ull v) {
    float2 r; asm("mov.b64 {%0,%1}, %2;" : "=f"(r.x), "=f"(r.y) : "l"(v)); return r;
}
__device__ __forceinline__ unsigned fkey(float f) {
    unsigned u = __float_as_uint(f);
    return (u & 0x80000000u) ? ~u : (u | 0x80000000u);
}
__device__ __forceinline__ float wredsum(float v) {
    #pragma unroll
    for (int o = 16; o; o >>= 1) v += __shfl_xor_sync(0xffffffffu, v, o);
    return v;
}
__device__ __forceinline__ float wredmax(float v) {
    #pragma unroll
    for (int o = 16; o; o >>= 1) v = fmaxf(v, __shfl_xor_sync(0xffffffffu, v, o));
    return v;
}

// ---------------- QKV GEMM (FFMA2) ----------------
// 64x64 tile, As pre-splatted float2 pairs, Bs plain [k][o].
__global__ __launch_bounds__(256) void qkv_gemm(const float* __restrict__ X,
                                                const float* __restrict__ W)
{
    __shared__ float2 As2[16*66];   // [k][m] splat pairs
    __shared__ float  Bs[16*68];    // [k][o]
    const int m0 = blockIdx.y * 64;
    const int o0 = blockIdx.x * 64;
    const int tid  = threadIdx.x;
    const int lrow = tid >> 2;
    const int lc4  = (tid & 3) << 2;
    const int tm = tid >> 4;
    const int to = tid & 15;

    ull acc[4][2];
    #pragma unroll
    for (int i = 0; i < 4; i++) { acc[i][0] = 0ull; acc[i][1] = 0ull; }

    for (int k0 = 0; k0 < C_; k0 += 16) {
        float4 av = *(const float4*)&X[(m0 + lrow) * C_ + k0 + lc4];
        float4 bv = *(const float4*)&W[(o0 + lrow) * C_ + k0 + lc4];
        __syncthreads();
        As2[(lc4+0)*66 + lrow] = make_float2(av.x, av.x);
        As2[(lc4+1)*66 + lrow] = make_float2(av.y, av.y);
        As2[(lc4+2)*66 + lrow] = make_float2(av.z, av.z);
        As2[(lc4+3)*66 + lrow] = make_float2(av.w, av.w);
        Bs[(lc4+0)*68 + lrow] = bv.x;
        Bs[(lc4+1)*68 + lrow] = bv.y;
        Bs[(lc4+2)*68 + lrow] = bv.z;
        Bs[(lc4+3)*68 + lrow] = bv.w;
        __syncthreads();
        #pragma unroll
        for (int kk = 0; kk < 16; kk++) {
            ull B0 = *(const ull*)&Bs[kk*68 + to*4];
            ull B1 = *(const ull*)&Bs[kk*68 + to*4 + 2];
            #pragma unroll
            for (int i = 0; i < 4; i++) {
                ull A = *(const ull*)&As2[kk*66 + tm*4 + i];
                ffma2(acc[i][0], A, B0);
                ffma2(acc[i][1], A, B1);
            }
        }
    }
    const int part = o0 / C_;
    const int h    = (o0 % C_) / DH;
    const int b    = m0 / N_;
    const int n0   = m0 % N_;
    if (part == 1) {
        float* kt = g_kT + ((b * H_ + h) * DH) * N_;
        #pragma unroll
        for (int i = 0; i < 4; i++) {
            int n = n0 + tm * 4 + i;
            float2 v0 = u2f(acc[i][0]), v1 = u2f(acc[i][1]);
            kt[(to*4+0)*N_ + n] = v0.x;
            kt[(to*4+1)*N_ + n] = v0.y;
            kt[(to*4+2)*N_ + n] = v1.x;
            kt[(to*4+3)*N_ + n] = v1.y;
        }
    } else {
        float* dst = (part == 0) ? g_q : g_v;
        #pragma unroll
        for (int i = 0; i < 4; i++) {
            int n = n0 + tm * 4 + i;
            float2 v0 = u2f(acc[i][0]), v1 = u2f(acc[i][1]);
            *(float4*)&dst[(((b * H_ + h) * N_) + n) * DH + to * 4] =
                make_float4(v0.x, v0.y, v1.x, v1.y);
        }
    }
}

// ---------------- Proj GEMM (FFMA2) ----------------
__global__ __launch_bounds__(256) void proj_gemm(const float* __restrict__ W,
                                                 const float* __restrict__ bias,
                                                 float* __restrict__ out)
{
    __shared__ float2 As2[16*66];
    __shared__ float  Bs[16*68];
    const int m0 = blockIdx.y * 64;
    const int o0 = blockIdx.x * 64;
    const int tid  = threadIdx.x;
    const int lrow = tid >> 2;
    const int lc4  = (tid & 3) << 2;
    const int tm = tid >> 4;
    const int to = tid & 15;

    const int m = m0 + lrow;
    const int bb_ = m >> 10;
    const int n   = m & 1023;

    ull acc[4][2];
    #pragma unroll
    for (int i = 0; i < 4; i++) { acc[i][0] = 0ull; acc[i][1] = 0ull; }

    for (int k0 = 0; k0 < C_; k0 += 16) {
        const int k = k0 + lc4;
        const int h = k >> 6;
        const int d = k & 63;
        float4 av = *(const float4*)&g_ctx[(((bb_ * H_ + h) * N_) + n) * DH + d];
        float4 bv = *(const float4*)&W[(o0 + lrow) * C_ + k0 + lc4];
        __syncthreads();
        As2[(lc4+0)*66 + lrow] = make_float2(av.x, av.x);
        As2[(lc4+1)*66 + lrow] = make_float2(av.y, av.y);
        As2[(lc4+2)*66 + lrow] = make_float2(av.z, av.z);
        As2[(lc4+3)*66 + lrow] = make_float2(av.w, av.w);
        Bs[(lc4+0)*68 + lrow] = bv.x;
        Bs[(lc4+1)*68 + lrow] = bv.y;
        Bs[(lc4+2)*68 + lrow] = bv.z;
        Bs[(lc4+3)*68 + lrow] = bv.w;
        __syncthreads();
        #pragma unroll
        for (int kk = 0; kk < 16; kk++) {
            ull B0 = *(const ull*)&Bs[kk*68 + to*4];
            ull B1 = *(const ull*)&Bs[kk*68 + to*4 + 2];
            #pragma unroll
            for (int i = 0; i < 4; i++) {
                ull A = *(const ull*)&As2[kk*66 + tm*4 + i];
                ffma2(acc[i][0], A, B0);
                ffma2(acc[i][1], A, B1);
            }
        }
    }
    float4 bsv = *(const float4*)&bias[o0 + to * 4];
    #pragma unroll
    for (int i = 0; i < 4; i++) {
        int mo = m0 + tm * 4 + i;
        float2 v0 = u2f(acc[i][0]), v1 = u2f(acc[i][1]);
        *(float4*)&out[mo * C_ + o0 + to * 4] =
            make_float4(v0.x + bsv.x, v0.y + bsv.y, v1.x + bsv.z, v1.y + bsv.w);
    }
}

// ---------------- Attention core (512 threads, 16 warps) ----------------
// smem: sQ2 8K | sS 64K | wl 8K | idxl 4K | mcnt 16K = 100K
#define SMEM_ATTN (8192 + 65536 + 8192 + 4096 + 16384)

__global__ __launch_bounds__(512, 1) void attn_kernel(const float* __restrict__ cnt,
                                                      const int* __restrict__ counter_p,
                                                      float* __restrict__ sd)
{
    extern __shared__ char smem[];
    float2*         sQ2  = (float2*)smem;                          // [16][64] splat pairs
    float*          sS   = (float*)(smem + 8192);                  // [16][1024]
    float*          wl   = (float*)(smem + 8192 + 65536);          // [16][128]
    unsigned short* idxl = (unsigned short*)(smem + 8192 + 65536 + 8192);
    unsigned char*  mcnt = (unsigned char*)(smem + 8192 + 65536 + 8192 + 4096);

    const int h    = blockIdx.y;
    const int q0   = blockIdx.x * QT;
    const int tid  = threadIdx.x;
    const int lane = tid & 31;
    const int w    = tid >> 5;
    const float logc = logf((float)(*counter_p) + 1.0f);

    for (int i = tid; i < QT*N_/4; i += 512) ((unsigned*)mcnt)[i] = 0u;

    for (int b = 0; b < B_; b++) {
        const float* KT = g_kT + ((b*H_ + h) * DH) * N_;
        const float* Vb = g_v  + ((b*H_ + h) * N_) * DH;
        __syncthreads();
        // build splat-scaled Q
        for (int i = tid; i < QT*DH; i += 512) {
            int r = i >> 6, kk = i & 63;
            float qv = g_q[((b*H_ + h)*N_ + q0 + r)*DH + kk] * 0.125f;
            sQ2[r*DH + kk] = make_float2(qv, qv);
        }
        __syncthreads();

        // ---- score GEMM: warp w -> rows [8*(w&1), +8), j block 128*(w>>1) ----
        {
            const int rg = (w & 1) * 8;
            const int jb = (w >> 1) * 128 + 4 * lane;
            ull acc[8][2];
            #pragma unroll
            for (int r = 0; r < 8; r++) { acc[r][0] = 0ull; acc[r][1] = 0ull; }
            #pragma unroll 4
            for (int kk = 0; kk < DH; kk += 2) {
                ulonglong2 kA = *(const ulonglong2*)&KT[kk*N_ + jb];
                ulonglong2 kB = *(const ulonglong2*)&KT[(kk+1)*N_ + jb];
                #pragma unroll
                for (int r = 0; r < 8; r++) {
                    ulonglong2 q2 = *(const ulonglong2*)&sQ2[(rg + r)*DH + kk];
                    ffma2(acc[r][0], q2.x, kA.x);
                    ffma2(acc[r][1], q2.x, kA.y);
                    ffma2(acc[r][0], q2.y, kB.x);
                    ffma2(acc[r][1], q2.y, kB.y);
                }
            }
            #pragma unroll
            for (int r = 0; r < 8; r++) {
                float2 v0 = u2f(acc[r][0]), v1 = u2f(acc[r][1]);
                *(float4*)&sS[(rg + r)*N_ + jb] = make_float4(v0.x, v0.y, v1.x, v1.y);
            }
        }
        __syncthreads();

        // ---- selection + context: warp w owns row r = w ----
        {
            const int r = w;
            const float* cr = cnt + (h*N_ + q0 + r) * N_;
            float sval[32];
            unsigned ukey[32];
            float m = -1e30f;
            #pragma unroll
            for (int u4 = 0; u4 < 8; u4++) {
                float4 sv = *(const float4*)&sS[r*N_ + u4*128 + 4*lane];
                float4 cv = *(const float4*)&cr[u4*128 + 4*lane];
                float ex = sqrtf(logc / (cv.x + 1e-6f));
                float ey = sqrtf(logc / (cv.y + 1e-6f));
                float ez = sqrtf(logc / (cv.z + 1e-6f));
                float ew = sqrtf(logc / (cv.w + 1e-6f));
                sval[u4*4+0] = sv.x; ukey[u4*4+0] = fkey(sv.x + ex);
                sval[u4*4+1] = sv.y; ukey[u4*4+1] = fkey(sv.y + ey);
                sval[u4*4+2] = sv.z; ukey[u4*4+2] = fkey(sv.z + ez);
                sval[u4*4+3] = sv.w; ukey[u4*4+3] = fkey(sv.w + ew);
                m = fmaxf(m, fmaxf(fmaxf(sv.x, sv.y), fmaxf(sv.z, sv.w)));
            }
            m = wredmax(m);
            float z = 0.f;
            #pragma unroll
            for (int u = 0; u < 32; u++) z += __expf(sval[u] - m);
            z = wredsum(z);

            // exact top-128 threshold via bitwise bisection (no atomics)
            unsigned T = 0;
            for (int bit = 31; bit >= 0; bit--) {
                unsigned Tc = T | (1u << bit);
                int c = 0;
                #pragma unroll
                for (int u = 0; u < 32; u++) c += (ukey[u] >= Tc) ? 1 : 0;
                c = __reduce_add_sync(0xffffffffu, c);
                if (c >= TOPK) T = Tc;
                if (c == TOPK) break;
            }

            // compaction scan
            int base = 0;
            float esum = 0.f;
            const unsigned lmask = (1u << lane) - 1u;
            #pragma unroll
            for (int u = 0; u < 32; u++) {
                bool sel = (ukey[u] >= T);
                unsigned bal = __ballot_sync(0xffffffffu, sel);
                if (sel) {
                    int pos = base + __popc(bal & lmask);
                    if (pos < TOPK) {
                        int j = (u >> 2)*128 + 4*lane + (u & 3);
                        float e = __expf(sval[u] - m);
                        esum += e;
                        idxl[r*TOPK + pos] = (unsigned short)j;
                        wl[r*TOPK + pos]   = e;
                        mcnt[r*N_ + j] = (unsigned char)(mcnt[r*N_ + j] + 1);
                    }
                }
                base += __popc(bal);
            }
            esum = wredsum(esum);
            float inv = 1.f / (esum + 1e-8f * z);
            for (int i = lane; i < TOPK; i += 32) wl[r*TOPK + i] *= inv;
            __syncwarp();

            // sparse context (warp-local lists, no cross-warp sync needed)
            float2 a = make_float2(0.f, 0.f);
            #pragma unroll 4
            for (int i = 0; i < TOPK; i++) {
                int   j  = idxl[r*TOPK + i];
                float ww = wl[r*TOPK + i];
                float2 v2 = *(const float2*)&Vb[j*DH + 2*lane];
                a.x += ww * v2.x;
                a.y += ww * v2.y;
            }
            *(float2*)&g_ctx[((b*H_ + h)*N_ + q0 + r)*DH + 2*lane] = a;
        }
    }
    __syncthreads();

    // score_delta
    for (int i = tid; i < QT*N_/4; i += 512) {
        int r  = i >> 8;
        int j4 = i & 255;
        unsigned mv = ((const unsigned*)mcnt)[r*256 + j4];
        float4 o;
        o.x = (float)( mv        & 255u);
        o.y = (float)((mv >>  8) & 255u);
        o.z = (float)((mv >> 16) & 255u);
        o.w = (float)((mv >> 24) & 255u);
        *(float4*)&sd[(h*N_ + q0 + r)*N_ + (j4 << 2)] = o;
    }
}

// ---------------- launch ----------------
extern "C" void kernel_launch(void* const* d_in, const int* in_sizes, int n_in,
                              void* d_out, int out_size)
{
    const float* x     = (const float*)d_in[0];
    const float* qkvw  = (const float*)d_in[1];
    const float* projw = (const float*)d_in[2];
    const float* projb = (const float*)d_in[3];
    const float* ucb   = (const float*)d_in[4];
    const int*   ctr   = (const int*)d_in[5];
    float* out = (float*)d_out;
    float* sd  = out + OUT0;

    cudaFuncSetAttribute(attn_kernel, cudaFuncAttributeMaxDynamicSharedMemorySize, SMEM_ATTN);

    qkv_gemm<<<dim3(36, 64), 256>>>(x, qkvw);
    attn_kernel<<<dim3(64, 12), 512, SMEM_ATTN>>>(ucb, ctr, sd);
    proj_gemm<<<dim3(12, 64), 256>>>(projw, projb, out);
}

// round 5
// speedup vs baseline: 1.8152x; 1.3014x over previous
#include <cuda_runtime.h>
#include <math.h>

#define B_ 4
#define N_ 1024
#define C_ 768
#define H_ 12
#define DH 64
#define QT 16
#define TOPK 128

#define OUT0 (B_*N_*C_)

typedef unsigned long long ull;

// ---------------- scratch ----------------
__device__ float g_q[B_*H_*N_*DH];
__device__ float g_kT[B_*H_*DH*N_];   // transposed: [b][h][d][n]
__device__ float g_v[B_*H_*N_*DH];
__device__ float g_ctx[B_*H_*N_*DH];

// ---------------- helpers ----------------
__device__ __forceinline__ void ffma2(ull& d, ull a, ull b) {
    asm("fma.rn.f32x2 %0, %1, %2, %0;" : "+l"(d) : "l"(a), "l"(b));
}
__device__ __forceinline__ ull splat(float f) {
    ull r; asm("mov.b64 %0, {%1,%1};" : "=l"(r) : "f"(f)); return r;
}
__device__ __forceinline__ float2 u2f(ull v) {
    float2 r; asm("mov.b64 {%0,%1}, %2;" : "=f"(r.x), "=f"(r.y) : "l"(v)); return r;
}
__device__ __forceinline__ unsigned fkey(float f) {
    unsigned u = __float_as_uint(f);
    return (u & 0x80000000u) ? ~u : (u | 0x80000000u);
}
__device__ __forceinline__ float wredsum(float v) {
    #pragma unroll
    for (int o = 16; o; o >>= 1) v += __shfl_xor_sync(0xffffffffu, v, o);
    return v;
}
__device__ __forceinline__ float wredmax(float v) {
    #pragma unroll
    for (int o = 16; o; o >>= 1) v = fmaxf(v, __shfl_xor_sync(0xffffffffu, v, o));
    return v;
}

#define AS 132   // padded smem row stride (floats), 16B-aligned

// =======================================================================
// 128x128x16 FFMA2 GEMM core: 256 threads, 8x8 outputs/thread,
// A splatted in registers. acc[r][c]: rows tm*4+{0..3}, 64+tm*4+{0..3};
// cols to*4+{0,1},{2,3}, 64+to*4+{0,1},{2,3}.
// =======================================================================
struct Frag { float4 a0, a1, b0, b1; };

__device__ __forceinline__ void gemm_tile(const float* As, const float* Bs,
                                          int tm, int to, ull acc[8][4])
{
    #pragma unroll
    for (int kk = 0; kk < 16; kk++) {
        float4 a0 = *(const float4*)&As[kk*AS + tm*4];
        float4 a1 = *(const float4*)&As[kk*AS + tm*4 + 64];
        ulonglong2 b0 = *(const ulonglong2*)&Bs[kk*AS + to*4];
        ulonglong2 b1 = *(const ulonglong2*)&Bs[kk*AS + to*4 + 64];
        ull as_[8];
        as_[0] = splat(a0.x); as_[1] = splat(a0.y);
        as_[2] = splat(a0.z); as_[3] = splat(a0.w);
        as_[4] = splat(a1.x); as_[5] = splat(a1.y);
        as_[6] = splat(a1.z); as_[7] = splat(a1.w);
        #pragma unroll
        for (int r = 0; r < 8; r++) {
            ffma2(acc[r][0], as_[r], b0.x);
            ffma2(acc[r][1], as_[r], b0.y);
            ffma2(acc[r][2], as_[r], b1.x);
            ffma2(acc[r][3], as_[r], b1.y);
        }
    }
}

__device__ __forceinline__ void stage_frag(float* As, float* Bs, int lrow, int lc4,
                                           const float4 fa[2], const float4 fb[2])
{
    #pragma unroll
    for (int it = 0; it < 2; it++) {
        int row = it*64 + lrow;
        As[(lc4+0)*AS + row] = fa[it].x;
        As[(lc4+1)*AS + row] = fa[it].y;
        As[(lc4+2)*AS + row] = fa[it].z;
        As[(lc4+3)*AS + row] = fa[it].w;
        Bs[(lc4+0)*AS + row] = fb[it].x;
        Bs[(lc4+1)*AS + row] = fb[it].y;
        Bs[(lc4+2)*AS + row] = fb[it].z;
        Bs[(lc4+3)*AS + row] = fb[it].w;
    }
}

// ---------------- QKV GEMM ----------------
__global__ __launch_bounds__(256, 2) void qkv_gemm(const float* __restrict__ X,
                                                   const float* __restrict__ W)
{
    __shared__ float As[16*AS];
    __shared__ float Bs[16*AS];
    const int m0 = blockIdx.y * 128;
    const int o0 = blockIdx.x * 128;
    const int tid  = threadIdx.x;
    const int lrow = tid >> 2;            // 0..63
    const int lc4  = (tid & 3) << 2;
    const int tm = tid >> 4;              // 0..15
    const int to = tid & 15;

    ull acc[8][4];
    #pragma unroll
    for (int r = 0; r < 8; r++)
        #pragma unroll
        for (int c = 0; c < 4; c++) acc[r][c] = 0ull;

    float4 fa[2], fb[2];
    #pragma unroll
    for (int it = 0; it < 2; it++) {
        fa[it] = *(const float4*)&X[(m0 + it*64 + lrow) * C_ + lc4];
        fb[it] = *(const float4*)&W[(o0 + it*64 + lrow) * C_ + lc4];
    }
    for (int k0 = 0; k0 < C_; k0 += 16) {
        __syncthreads();
        stage_frag(As, Bs, lrow, lc4, fa, fb);
        __syncthreads();
        if (k0 + 16 < C_) {
            #pragma unroll
            for (int it = 0; it < 2; it++) {
                fa[it] = *(const float4*)&X[(m0 + it*64 + lrow) * C_ + k0 + 16 + lc4];
                fb[it] = *(const float4*)&W[(o0 + it*64 + lrow) * C_ + k0 + 16 + lc4];
            }
        }
        gemm_tile(As, Bs, tm, to, acc);
    }

    const int part = o0 / C_;             // o-tile never straddles a part
    const int h0   = (o0 % C_) / DH;      // cols cover heads h0, h0+1
    const int b    = m0 >> 10;
    const int n0   = m0 & 1023;
    const int d4   = to * 4;              // d within head, same for both col groups

    if (part == 1) {
        float* kt = g_kT + ((b * H_ + h0) * DH) * N_;       // head h0
        float* kt1 = kt + DH * N_;                          // head h0+1
        #pragma unroll
        for (int rg = 0; rg < 2; rg++)
            #pragma unroll
            for (int i = 0; i < 4; i++) {
                int n = n0 + rg*64 + tm*4 + i;
                int r = rg*4 + i;
                float2 v0 = u2f(acc[r][0]), v1 = u2f(acc[r][1]);
                float2 v2 = u2f(acc[r][2]), v3 = u2f(acc[r][3]);
                kt [(d4+0)*N_ + n] = v0.x; kt [(d4+1)*N_ + n] = v0.y;
                kt [(d4+2)*N_ + n] = v1.x; kt [(d4+3)*N_ + n] = v1.y;
                kt1[(d4+0)*N_ + n] = v2.x; kt1[(d4+1)*N_ + n] = v2.y;
                kt1[(d4+2)*N_ + n] = v3.x; kt1[(d4+3)*N_ + n] = v3.y;
            }
    } else {
        float* dst = (part == 0) ? g_q : g_v;
        float* d0 = dst + (((b * H_ + h0)     * N_)) * DH;
        float* d1 = dst + (((b * H_ + h0 + 1) * N_)) * DH;
        #pragma unroll
        for (int rg = 0; rg < 2; rg++)
            #pragma unroll
            for (int i = 0; i < 4; i++) {
                int n = n0 + rg*64 + tm*4 + i;
                int r = rg*4 + i;
                float2 v0 = u2f(acc[r][0]), v1 = u2f(acc[r][1]);
                float2 v2 = u2f(acc[r][2]), v3 = u2f(acc[r][3]);
                *(float4*)&d0[n*DH + d4] = make_float4(v0.x, v0.y, v1.x, v1.y);
                *(float4*)&d1[n*DH + d4] = make_float4(v2.x, v2.y, v3.x, v3.y);
            }
    }
}

// ---------------- Proj GEMM ----------------
__global__ __launch_bounds__(256, 2) void proj_gemm(const float* __restrict__ W,
                                                    const float* __restrict__ bias,
                                                    float* __restrict__ out)
{
    __shared__ float As[16*AS];
    __shared__ float Bs[16*AS];
    const int m0 = blockIdx.y * 128;
    const int o0 = blockIdx.x * 128;
    const int tid  = threadIdx.x;
    const int lrow = tid >> 2;
    const int lc4  = (tid & 3) << 2;
    const int tm = tid >> 4;
    const int to = tid & 15;

    ull acc[8][4];
    #pragma unroll
    for (int r = 0; r < 8; r++)
        #pragma unroll
        for (int c = 0; c < 4; c++) acc[r][c] = 0ull;

    float4 fa[2], fb[2];
    #pragma unroll
    for (int it = 0; it < 2; it++) {
        int m = m0 + it*64 + lrow;
        int bb = m >> 10, n = m & 1023;
        int h = lc4 >> 6, d = lc4 & 63;
        fa[it] = *(const float4*)&g_ctx[(((bb * H_ + h) * N_) + n) * DH + d];
        fb[it] = *(const float4*)&W[(o0 + it*64 + lrow) * C_ + lc4];
    }
    for (int k0 = 0; k0 < C_; k0 += 16) {
        __syncthreads();
        stage_frag(As, Bs, lrow, lc4, fa, fb);
        __syncthreads();
        if (k0 + 16 < C_) {
            int k = k0 + 16 + lc4;
            int h = k >> 6, d = k & 63;
            #pragma unroll
            for (int it = 0; it < 2; it++) {
                int m = m0 + it*64 + lrow;
                int bb = m >> 10, n = m & 1023;
                fa[it] = *(const float4*)&g_ctx[(((bb * H_ + h) * N_) + n) * DH + d];
                fb[it] = *(const float4*)&W[(o0 + it*64 + lrow) * C_ + k0 + 16 + lc4];
            }
        }
        gemm_tile(As, Bs, tm, to, acc);
    }

    float4 bs0 = *(const float4*)&bias[o0 + to*4];
    float4 bs1 = *(const float4*)&bias[o0 + 64 + to*4];
    #pragma unroll
    for (int rg = 0; rg < 2; rg++)
        #pragma unroll
        for (int i = 0; i < 4; i++) {
            int mo = m0 + rg*64 + tm*4 + i;
            int r = rg*4 + i;
            float2 v0 = u2f(acc[r][0]), v1 = u2f(acc[r][1]);
            float2 v2 = u2f(acc[r][2]), v3 = u2f(acc[r][3]);
            *(float4*)&out[mo * C_ + o0 + to*4] =
                make_float4(v0.x + bs0.x, v0.y + bs0.y, v1.x + bs0.z, v1.y + bs0.w);
            *(float4*)&out[mo * C_ + o0 + 64 + to*4] =
                make_float4(v2.x + bs1.x, v2.y + bs1.y, v3.x + bs1.z, v3.y + bs1.w);
        }
}

// ---------------- Attention core (unchanged from round 4) ----------------
#define SMEM_ATTN (8192 + 65536 + 8192 + 4096 + 16384)

__global__ __launch_bounds__(512, 1) void attn_kernel(const float* __restrict__ cnt,
                                                      const int* __restrict__ counter_p,
                                                      float* __restrict__ sd)
{
    extern __shared__ char smem[];
    float2*         sQ2  = (float2*)smem;
    float*          sS   = (float*)(smem + 8192);
    float*          wl   = (float*)(smem + 8192 + 65536);
    unsigned short* idxl = (unsigned short*)(smem + 8192 + 65536 + 8192);
    unsigned char*  mcnt = (unsigned char*)(smem + 8192 + 65536 + 8192 + 4096);

    const int h    = blockIdx.y;
    const int q0   = blockIdx.x * QT;
    const int tid  = threadIdx.x;
    const int lane = tid & 31;
    const int w    = tid >> 5;
    const float logc = logf((float)(*counter_p) + 1.0f);

    for (int i = tid; i < QT*N_/4; i += 512) ((unsigned*)mcnt)[i] = 0u;

    for (int b = 0; b < B_; b++) {
        const float* KT = g_kT + ((b*H_ + h) * DH) * N_;
        const float* Vb = g_v  + ((b*H_ + h) * N_) * DH;
        __syncthreads();
        for (int i = tid; i < QT*DH; i += 512) {
            int r = i >> 6, kk = i & 63;
            float qv = g_q[((b*H_ + h)*N_ + q0 + r)*DH + kk] * 0.125f;
            sQ2[r*DH + kk] = make_float2(qv, qv);
        }
        __syncthreads();

        {
            const int rg = (w & 1) * 8;
            const int jb = (w >> 1) * 128 + 4 * lane;
            ull acc[8][2];
            #pragma unroll
            for (int r = 0; r < 8; r++) { acc[r][0] = 0ull; acc[r][1] = 0ull; }
            #pragma unroll 4
            for (int kk = 0; kk < DH; kk += 2) {
                ulonglong2 kA = *(const ulonglong2*)&KT[kk*N_ + jb];
                ulonglong2 kB = *(const ulonglong2*)&KT[(kk+1)*N_ + jb];
                #pragma unroll
                for (int r = 0; r < 8; r++) {
                    ulonglong2 q2 = *(const ulonglong2*)&sQ2[(rg + r)*DH + kk];
                    ffma2(acc[r][0], q2.x, kA.x);
                    ffma2(acc[r][1], q2.x, kA.y);
                    ffma2(acc[r][0], q2.y, kB.x);
                    ffma2(acc[r][1], q2.y, kB.y);
                }
            }
            #pragma unroll
            for (int r = 0; r < 8; r++) {
                float2 v0 = u2f(acc[r][0]), v1 = u2f(acc[r][1]);
                *(float4*)&sS[(rg + r)*N_ + jb] = make_float4(v0.x, v0.y, v1.x, v1.y);
            }
        }
        __syncthreads();

        {
            const int r = w;
            const float* cr = cnt + (h*N_ + q0 + r) * N_;
            float sval[32];
            unsigned ukey[32];
            float m = -1e30f;
            #pragma unroll
            for (int u4 = 0; u4 < 8; u4++) {
                float4 sv = *(const float4*)&sS[r*N_ + u4*128 + 4*lane];
                float4 cv = *(const float4*)&cr[u4*128 + 4*lane];
                float ex = sqrtf(logc / (cv.x + 1e-6f));
                float ey = sqrtf(logc / (cv.y + 1e-6f));
                float ez = sqrtf(logc / (cv.z + 1e-6f));
                float ew = sqrtf(logc / (cv.w + 1e-6f));
                sval[u4*4+0] = sv.x; ukey[u4*4+0] = fkey(sv.x + ex);
                sval[u4*4+1] = sv.y; ukey[u4*4+1] = fkey(sv.y + ey);
                sval[u4*4+2] = sv.z; ukey[u4*4+2] = fkey(sv.z + ez);
                sval[u4*4+3] = sv.w; ukey[u4*4+3] = fkey(sv.w + ew);
                m = fmaxf(m, fmaxf(fmaxf(sv.x, sv.y), fmaxf(sv.z, sv.w)));
            }
            m = wredmax(m);
            float z = 0.f;
            #pragma unroll
            for (int u = 0; u < 32; u++) z += __expf(sval[u] - m);
            z = wredsum(z);

            unsigned T = 0;
            for (int bit = 31; bit >= 0; bit--) {
                unsigned Tc = T | (1u << bit);
                int c = 0;
                #pragma unroll
                for (int u = 0; u < 32; u++) c += (ukey[u] >= Tc) ? 1 : 0;
                c = __reduce_add_sync(0xffffffffu, c);
                if (c >= TOPK) T = Tc;
                if (c == TOPK) break;
            }

            int base = 0;
            float esum = 0.f;
            const unsigned lmask = (1u << lane) - 1u;
            #pragma unroll
            for (int u = 0; u < 32; u++) {
                bool sel = (ukey[u] >= T);
                unsigned bal = __ballot_sync(0xffffffffu, sel);
                if (sel) {
                    int pos = base + __popc(bal & lmask);
                    if (pos < TOPK) {
                        int j = (u >> 2)*128 + 4*lane + (u & 3);
                        float e = __expf(sval[u] - m);
                        esum += e;
                        idxl[r*TOPK + pos] = (unsigned short)j;
                        wl[r*TOPK + pos]   = e;
                        mcnt[r*N_ + j] = (unsigned char)(mcnt[r*N_ + j] + 1);
                    }
                }
                base += __popc(bal);
            }
            esum = wredsum(esum);
            float inv = 1.f / (esum + 1e-8f * z);
            for (int i = lane; i < TOPK; i += 32) wl[r*TOPK + i] *= inv;
            __syncwarp();

            float2 a = make_float2(0.f, 0.f);
            #pragma unroll 4
            for (int i = 0; i < TOPK; i++) {
                int   j  = idxl[r*TOPK + i];
                float ww = wl[r*TOPK + i];
                float2 v2 = *(const float2*)&Vb[j*DH + 2*lane];
                a.x += ww * v2.x;
                a.y += ww * v2.y;
            }
            *(float2*)&g_ctx[((b*H_ + h)*N_ + q0 + r)*DH + 2*lane] = a;
        }
    }
    __syncthreads();

    for (int i = tid; i < QT*N_/4; i += 512) {
        int r  = i >> 8;
        int j4 = i & 255;
        unsigned mv = ((const unsigned*)mcnt)[r*256 + j4];
        float4 o;
        o.x = (float)( mv        & 255u);
        o.y = (float)((mv >>  8) & 255u);
        o.z = (float)((mv >> 16) & 255u);
        o.w = (float)((mv >> 24) & 255u);
        *(float4*)&sd[(h*N_ + q0 + r)*N_ + (j4 << 2)] = o;
    }
}

// ---------------- launch ----------------
extern "C" void kernel_launch(void* const* d_in, const int* in_sizes, int n_in,
                              void* d_out, int out_size)
{
    const float* x     = (const float*)d_in[0];
    const float* qkvw  = (const float*)d_in[1];
    const float* projw = (const float*)d_in[2];
    const float* projb = (const float*)d_in[3];
    const float* ucb   = (const float*)d_in[4];
    const int*   ctr   = (const int*)d_in[5];
    float* out = (float*)d_out;
    float* sd  = out + OUT0;

    cudaFuncSetAttribute(attn_kernel, cudaFuncAttributeMaxDynamicSharedMemorySize, SMEM_ATTN);

    qkv_gemm<<<dim3(18, 32), 256>>>(x, qkvw);
    attn_kernel<<<dim3(64, 12), 512, SMEM_ATTN>>>(ucb, ctr, sd);
    proj_gemm<<<dim3(6, 32), 256>>>(projw, projb, out);
}